// round 14
// baseline (speedup 1.0000x reference)
#include <cuda_runtime.h>
#include <math.h>
#include <stdint.h>

#define TT 512
#define DD 512
#define HH 1024
#define VV 8192
#define BB 16
#define BLANKTOK 8191
#define NEGF (-99999.0f)
#define EXPANDF 10.0f
#define NBLK 128
#define NTHR 512
#define JP 1026                       // packed-act row stride, u64 units (EVEN: 16B align)
#define PS 20                         // partial slot stride (floats), mod 4 == 0
#define WOFFU (16 * JP)               // u64 offset of weight stage buffers
#define DYN_SMEM (16 * JP * 8 + 4 * 16384)   // 131328 + 65536 = 196864 bytes

// ---------------- device globals ----------------
__device__ __align__(16) float g_enc[TT * HH];
__device__ __align__(16) float g_pmax[BB * NBLK];
__device__ __align__(16) float g_pnb[BB * NBLK];
__device__ float g_mf[BB];
__device__ float g_blanklogit[BB];
__device__ __align__(16) double g_psum[BB * NBLK];
__device__ float g_scores2[2][BB];
__device__ __align__(16) float g_h[2][BB * HH];
__device__ __align__(16) float g_c[2][BB * HH];
__device__ int g_tokens[2][BB * TT];
__device__ unsigned long long g_part[NBLK * BB];
__device__ float g_g0[4 * HH];
__device__ unsigned g_bar_gen;
__device__ unsigned g_bar_cnt;

// ---------------- helpers ----------------
__device__ __forceinline__ float sigf(float x) {
    return (float)(1.0 / (1.0 + exp(-(double)x)));
}
__device__ __forceinline__ float tanh_acc(float x) {
    return (float)tanh((double)x);
}
__device__ __forceinline__ unsigned ordf(float f) {
    unsigned u = __float_as_uint(f);
    return (u & 0x80000000u) ? ~u : (u | 0x80000000u);
}
__device__ __forceinline__ float unordf(unsigned s) {
    return (s & 0x80000000u) ? __uint_as_float(s & 0x7FFFFFFFu) : __uint_as_float(~s);
}
__device__ __forceinline__ unsigned long long mkkey(float v, unsigned idx) {
    return ((unsigned long long)ordf(v) << 32) | (unsigned long long)(0xFFFFFFFFu - idx);
}
__device__ __forceinline__ void ffma2(unsigned long long& d, unsigned long long a,
                                      unsigned long long b) {
    asm("fma.rn.f32x2 %0, %1, %2, %0;" : "+l"(d) : "l"(a), "l"(b));
}
__device__ __forceinline__ unsigned long long pk2(float x) {
    unsigned long long r;
    asm("mov.b64 %0, {%1, %1};" : "=l"(r) : "r"(__float_as_uint(x)));
    return r;
}
__device__ __forceinline__ void gridbar() {
    __syncthreads();
    if (threadIdx.x == 0) {
        __threadfence();
        unsigned gen = *(volatile unsigned*)&g_bar_gen;
        unsigned a = atomicAdd(&g_bar_cnt, 1u);
        if (a == NBLK - 1u) {
            g_bar_cnt = 0u;
            __threadfence();
            *(volatile unsigned*)&g_bar_gen = gen + 1u;
        } else {
            while (*(volatile unsigned*)&g_bar_gen == gen) { }
            __threadfence();
        }
    }
    __syncthreads();
}
// cp.async helpers
__device__ __forceinline__ void cpa16(unsigned dst, const void* src) {
    asm volatile("cp.async.cg.shared.global [%0], [%1], 16;" :: "r"(dst), "l"(src));
}
template <int N>
__device__ __forceinline__ void cpwait() {
    asm volatile("cp.async.wait_group %0;" :: "n"(N));
}
#define CP_COMMIT() asm volatile("cp.async.commit_group;")

// ======== LSTM GEMM macros (identical to R10) ========
#define LOADW(W, PTR, STRIDE) do {                                          \
    _Pragma("unroll")                                                       \
    for (int _u = 0; _u < 4; _u++)                                          \
        W[_u] = *(const ulonglong2*)((PTR) + (size_t)_u * (STRIDE));        \
    (PTR) += (size_t)4 * (STRIDE);                                          \
} while (0)

#define CONSUME(W, KOFF) do {                                               \
    ulonglong2 xa = *(const ulonglong2*)(a0 + (KOFF));                      \
    ulonglong2 xb = *(const ulonglong2*)(a1 + (KOFF));                      \
    ulonglong2 xc = *(const ulonglong2*)(a2 + (KOFF));                      \
    ulonglong2 xd = *(const ulonglong2*)(a3 + (KOFF));                      \
    ffma2(c00, xa.x, W[0].x); ffma2(c01, xa.x, W[0].y);                     \
    ffma2(c10, xb.x, W[0].x); ffma2(c11, xb.x, W[0].y);                     \
    ffma2(c20, xc.x, W[0].x); ffma2(c21, xc.x, W[0].y);                     \
    ffma2(c30, xd.x, W[0].x); ffma2(c31, xd.x, W[0].y);                     \
    ffma2(c00, xa.y, W[1].x); ffma2(c01, xa.y, W[1].y);                     \
    ffma2(c10, xb.y, W[1].x); ffma2(c11, xb.y, W[1].y);                     \
    ffma2(c20, xc.y, W[1].x); ffma2(c21, xc.y, W[1].y);                     \
    ffma2(c30, xd.y, W[1].x); ffma2(c31, xd.y, W[1].y);                     \
    ulonglong2 ya = *(const ulonglong2*)(a0 + (KOFF) + 2);                  \
    ulonglong2 yb = *(const ulonglong2*)(a1 + (KOFF) + 2);                  \
    ulonglong2 yc = *(const ulonglong2*)(a2 + (KOFF) + 2);                  \
    ulonglong2 yd = *(const ulonglong2*)(a3 + (KOFF) + 2);                  \
    ffma2(c00, ya.x, W[2].x); ffma2(c01, ya.x, W[2].y);                     \
    ffma2(c10, yb.x, W[2].x); ffma2(c11, yb.x, W[2].y);                     \
    ffma2(c20, yc.x, W[2].x); ffma2(c21, yc.x, W[2].y);                     \
    ffma2(c30, yd.x, W[2].x); ffma2(c31, yd.x, W[2].y);                     \
    ffma2(c00, ya.y, W[3].x); ffma2(c01, ya.y, W[3].y);                     \
    ffma2(c10, yb.y, W[3].x); ffma2(c11, yb.y, W[3].y);                     \
    ffma2(c20, yc.y, W[3].x); ffma2(c21, yc.y, W[3].y);                     \
    ffma2(c30, yd.y, W[3].x); ffma2(c31, yd.y, W[3].y);                     \
} while (0)

#define STORE_PARTIALS(SRED, BASE) do {                                     \
    *(ulonglong2*)&(SRED)[(BASE) + 0]  = make_ulonglong2(c00, c01);         \
    *(ulonglong2*)&(SRED)[(BASE) + 4]  = make_ulonglong2(c10, c11);         \
    *(ulonglong2*)&(SRED)[(BASE) + 8]  = make_ulonglong2(c20, c21);         \
    *(ulonglong2*)&(SRED)[(BASE) + 12] = make_ulonglong2(c30, c31);         \
} while (0)

// fill one 8-k weight stage (16KB) via cp.async; layout [kc][kl(8)][col(64)] f32
#define FILL_STAGE(S) do {                                                   \
    unsigned _dstb = smem_u32 + (unsigned)((WOFFU + ((S) & 3) * 2048) * 8);  \
    _Pragma("unroll")                                                        \
    for (int _j = 0; _j < 2; _j++) {                                         \
        int _fi = _j * NTHR + tid;                                           \
        int _kcw = _fi >> 7, _kl = (_fi >> 4) & 7, _c4 = _fi & 15;           \
        const float* _src = jW + (size_t)(_kcw * 128 + (S) * 8 + _kl) * VV   \
                          + blk * 64 + _c4 * 4;                              \
        cpa16(_dstb + (unsigned)_fi * 16u, _src);                            \
    }                                                                        \
    CP_COMMIT();                                                             \
} while (0)

// ---------------- persistent kernel ----------------
__global__ void __launch_bounds__(NTHR, 1)
rnnt_persist(const float* __restrict__ inp,  const float* __restrict__ encW,
             const float* __restrict__ encb, const float* __restrict__ embed,
             const float* __restrict__ Wx,   const float* __restrict__ Wh,
             const float* __restrict__ blstm,const float* __restrict__ jW,
             const float* __restrict__ jb,   float* __restrict__ out) {
    extern __shared__ unsigned long long smp[];

    __shared__ float xr[DD];
    __shared__ float s_logits[BB][65];
    __shared__ float s_gates[BB][33];
    __shared__ float s_m[BB], s_nbm[BB], s_lz[BB], s_thr[BB], s_blk[BB], s_sc[BB];
    __shared__ double s_Z[BB];
    __shared__ float s_nbsc[BB], s_newsc[BB];
    __shared__ int s_nbhypo[BB], s_nbtok[BB], s_isblank[BB], s_bsel[BB], s_nsel[BB];
    __shared__ unsigned long long s_stk[256];
    __shared__ float s_act[128][4];
    __shared__ float nh_s[BB][8], nc_s[BB][8];

    const int tid = threadIdx.x;
    const int blk = blockIdx.x;
    const int lane = tid & 31;
    const int wrp = tid >> 5;   // 0..15 = beam row for per-beam phases

    unsigned smem_u32;
    asm("{ .reg .u64 t; cvta.to.shared.u64 t, %1; cvt.u32.u64 %0, t; }"
        : "=r"(smem_u32) : "l"(smp));

    // ================= prologue =================
    for (int t0 = blk; t0 < TT; t0 += NBLK) {
        for (int i = tid; i < DD; i += NTHR) xr[i] = inp[t0 * DD + i];
        __syncthreads();
        int col = tid * 2;
        float a0 = 0.f, a1 = 0.f;
#pragma unroll 4
        for (int k = 0; k < DD; k++) {
            float2 w = *(const float2*)&encW[(size_t)k * HH + col];
            a0 += xr[k] * w.x; a1 += xr[k] * w.y;
        }
        g_enc[(size_t)t0 * HH + col]     = a0 + encb[col];
        g_enc[(size_t)t0 * HH + col + 1] = a1 + encb[col + 1];
        __syncthreads();
    }
    gridbar();
    if (blk < 8) {
        int col = blk * NTHR + tid;
        float acc = 0.f;
        const float* er = &embed[(size_t)BLANKTOK * HH];
#pragma unroll 4
        for (int k = 0; k < HH; k++) acc += er[k] * Wx[(size_t)k * 4 * HH + col];
        g_g0[col] = acc + blstm[col];
    } else if (blk < 24) {
        int e = (blk - 8) * NTHR + tid;
        g_tokens[0][e] = BLANKTOK;
    } else if (blk == 24 && tid < BB) {
        g_scores2[0][tid] = (tid == 0) ? 0.f : -1000000000.0f;
    }
    gridbar();
    if (blk < 2) {
        int u = blk * NTHR + tid;
        float gi = g_g0[u], gg = g_g0[2 * HH + u], go = g_g0[3 * HH + u];
        float c0 = sigf(gi) * tanh_acc(gg);
        float h0 = sigf(go) * tanh_acc(c0);
        for (int b = 0; b < BB; b++) {
            g_h[0][b * HH + u] = h0;
            g_c[0][b * HH + u] = c0;
        }
    }
    gridbar();

    // ================= main loop =================
    for (int t = 0; t < TT; t++) {
        const int par = t & 1, np = par ^ 1;

        // ---- ph1: joint GEMM (cp.async weight staging) + logits + local stats ----
        {
            const int quad = tid & 15, rg = (tid >> 4) & 3, kc = tid >> 6;
            // prime 3 weight stages (latency overlaps the act fill)
            FILL_STAGE(0);
            FILL_STAGE(1);
            FILL_STAGE(2);

            const float* hs = g_h[par];
            const float* et = &g_enc[(size_t)t * HH];
#pragma unroll
            for (int j = 0; j < 8; j++) {
                int unit = j * NTHR + tid;
                int row = unit >> 8, k = (unit & 255) * 4;
                float4 ev = *(const float4*)&et[k];
                float4 hv = *(const float4*)&hs[row * HH + k];
                float v0 = ev.x + hv.x; v0 = v0 > 0.f ? v0 : 0.f;
                float v1 = ev.y + hv.y; v1 = v1 > 0.f ? v1 : 0.f;
                float v2 = ev.z + hv.z; v2 = v2 > 0.f ? v2 : 0.f;
                float v3 = ev.w + hv.w; v3 = v3 > 0.f ? v3 : 0.f;
                ulonglong2* dst = (ulonglong2*)(smp + row * JP + k);
                dst[0] = make_ulonglong2(pk2(v0), pk2(v1));
                dst[1] = make_ulonglong2(pk2(v2), pk2(v3));
            }
            __syncthreads();
            const unsigned long long* a0 = smp + (rg * 4 + 0) * JP + kc * 128;
            const unsigned long long* a1 = a0 + JP;
            const unsigned long long* a2 = a1 + JP;
            const unsigned long long* a3 = a2 + JP;
            unsigned long long c00=0,c01=0,c10=0,c11=0,c20=0,c21=0,c30=0,c31=0;
#pragma unroll 1
            for (int it = 0; it < 16; it++) {
                if (it <= 13) cpwait<2>();
                else if (it == 14) cpwait<1>();
                else cpwait<0>();
                __syncthreads();
                const unsigned long long* wsm =
                    smp + WOFFU + (size_t)(it & 3) * 2048 + kc * 256 + quad * 2;
#pragma unroll
                for (int u2 = 0; u2 < 8; u2 += 2) {
                    ulonglong2 w0 = *(const ulonglong2*)(wsm + u2 * 32);
                    ulonglong2 w1 = *(const ulonglong2*)(wsm + (u2 + 1) * 32);
                    ulonglong2 xa = *(const ulonglong2*)(a0 + it * 8 + u2);
                    ulonglong2 xb = *(const ulonglong2*)(a1 + it * 8 + u2);
                    ulonglong2 xc = *(const ulonglong2*)(a2 + it * 8 + u2);
                    ulonglong2 xd = *(const ulonglong2*)(a3 + it * 8 + u2);
                    // k = it*8+u2  (one FMA per accumulator, k ascending)
                    ffma2(c00, xa.x, w0.x); ffma2(c01, xa.x, w0.y);
                    ffma2(c10, xb.x, w0.x); ffma2(c11, xb.x, w0.y);
                    ffma2(c20, xc.x, w0.x); ffma2(c21, xc.x, w0.y);
                    ffma2(c30, xd.x, w0.x); ffma2(c31, xd.x, w0.y);
                    // k = it*8+u2+1
                    ffma2(c00, xa.y, w1.x); ffma2(c01, xa.y, w1.y);
                    ffma2(c10, xb.y, w1.x); ffma2(c11, xb.y, w1.y);
                    ffma2(c20, xc.y, w1.x); ffma2(c21, xc.y, w1.y);
                    ffma2(c30, xd.y, w1.x); ffma2(c31, xd.y, w1.y);
                }
                if (it < 13) FILL_STAGE(it + 3);
            }
            __syncthreads();
            float* sred = (float*)smp;
            STORE_PARTIALS(sred, (kc * 64 + rg * 16 + quad) * PS);
            __syncthreads();
            if (tid < 256) {
                int row = tid >> 4, quado = tid & 15;
                int rgo = row >> 2, r = row & 3;
                float s0 = 0.f, s1 = 0.f, s2 = 0.f, s3 = 0.f;
#pragma unroll
                for (int k8 = 0; k8 < 8; k8++) {
                    float4 f = *(const float4*)
                        &sred[(k8 * 64 + rgo * 16 + quado) * PS + r * 4];
                    s0 += f.x; s1 += f.y; s2 += f.z; s3 += f.w;
                }
                int c64 = quado * 4;
                s_logits[row][c64 + 0] = s0 + jb[blk * 64 + c64 + 0];
                s_logits[row][c64 + 1] = s1 + jb[blk * 64 + c64 + 1];
                s_logits[row][c64 + 2] = s2 + jb[blk * 64 + c64 + 2];
                s_logits[row][c64 + 3] = s3 + jb[blk * 64 + c64 + 3];
            }
            __syncthreads();
            float x0 = s_logits[wrp][lane], x1 = s_logits[wrp][lane + 32];
            float pm = fmaxf(x0, x1);
            float nb0 = (blk == 0 && lane < 4) ? -1e30f : x0;
            float nb1 = (blk == NBLK - 1 && lane == 31) ? -1e30f : x1;
            float pn = fmaxf(nb0, nb1);
            for (int off = 16; off; off >>= 1) {
                pm = fmaxf(pm, __shfl_xor_sync(0xffffffffu, pm, off));
                pn = fmaxf(pn, __shfl_xor_sync(0xffffffffu, pn, off));
            }
            double d = (double)expf(x0 - pm) + (double)expf(x1 - pm);
            for (int off = 16; off; off >>= 1)
                d += __shfl_down_sync(0xffffffffu, d, off);
            if (lane == 0) {
                g_pmax[wrp * NBLK + blk] = pm;
                g_pnb[wrp * NBLK + blk]  = pn;
                g_psum[wrp * NBLK + blk] = d;
                if (blk == 0)
                    g_mf[wrp] = fmaxf(fmaxf(s_logits[wrp][0], s_logits[wrp][1]),
                                      fmaxf(s_logits[wrp][2], s_logits[wrp][3]));
                if (blk == NBLK - 1) g_blanklogit[wrp] = s_logits[wrp][63];
            }
        }
        gridbar();

        // ---- ph2: combine stats (lane-packed FP64 log) + candidates + block top-16 ----
        {
            const float* pma = &g_pmax[wrp * NBLK];
            const float* pna = &g_pnb[wrp * NBLK];
            const double* psa = &g_psum[wrp * NBLK];
            float pa0 = pma[lane * 4 + 0], pa1 = pma[lane * 4 + 1];
            float pa2 = pma[lane * 4 + 2], pa3 = pma[lane * 4 + 3];
            float pm = fmaxf(fmaxf(pa0, pa1), fmaxf(pa2, pa3));
            float q0 = pna[lane * 4 + 0], q1 = pna[lane * 4 + 1];
            float q2 = pna[lane * 4 + 2], q3 = pna[lane * 4 + 3];
            float pn = fmaxf(fmaxf(q0, q1), fmaxf(q2, q3));
            for (int off = 16; off; off >>= 1) {
                pm = fmaxf(pm, __shfl_xor_sync(0xffffffffu, pm, off));
                pn = fmaxf(pn, __shfl_xor_sync(0xffffffffu, pn, off));
            }
            double Z = psa[lane * 4 + 0] * (double)expf(pa0 - pm)
                     + psa[lane * 4 + 1] * (double)expf(pa1 - pm)
                     + psa[lane * 4 + 2] * (double)expf(pa2 - pm)
                     + psa[lane * 4 + 3] * (double)expf(pa3 - pm);
            for (int off = 16; off; off >>= 1)
                Z += __shfl_xor_sync(0xffffffffu, Z, off);
            if (lane == 0) {
                s_m[wrp] = pm;
                s_nbm[wrp] = pn;
                s_Z[wrp] = Z;
                s_sc[wrp] = g_scores2[par][wrp];
            }
            __syncthreads();
            if (wrp == 0 && lane < BB) {
                float m = s_m[lane];
                float lz = (float)log(s_Z[lane]);
                s_lz[lane] = lz;
                float t1 = (s_nbm[lane] - m) - lz;
                float t2 = ((g_mf[lane] - m) - lz) + NEGF;
                s_thr[lane] = fmaxf(t1, t2) - EXPANDF;
                s_blk[lane] = (g_blanklogit[lane] - m) - lz;
            }
            __syncthreads();
            float m = s_m[wrp], lz = s_lz[wrp], thr = s_thr[wrp], sc = s_sc[wrp];
            int c0 = lane, c1 = lane + 32;
            float x0 = s_logits[wrp][c0], x1 = s_logits[wrp][c1];
            float lp0 = (x0 - m) - lz;
            if (blk == 0 && c0 < 4) lp0 += NEGF;
            float lp1 = (x1 - m) - lz;
            float nb0 = lp0 > thr ? lp0 : NEGF;
            float nb1 = lp1 > thr ? lp1 : NEGF;
            int v0 = blk * 64 + c0, v1 = blk * 64 + c1;
            unsigned long long k0 = mkkey(sc + nb0, (unsigned)(wrp * (VV - 1) + v0));
            unsigned long long k1 = (v1 == VV - 1) ? 0ULL
                                  : mkkey(sc + nb1, (unsigned)(wrp * (VV - 1) + v1));
            for (int r = 0; r < BB; r++) {
                unsigned long long loc = k0 > k1 ? k0 : k1;
                for (int off = 16; off; off >>= 1) {
                    unsigned long long o = __shfl_xor_sync(0xffffffffu, loc, off);
                    if (o > loc) loc = o;
                }
                if (lane == r) s_stk[wrp * 16 + r] = loc;
                if (k0 == loc) k0 = 0ULL;
                if (k1 == loc) k1 = 0ULL;
            }
            __syncthreads();
            if (wrp == 0) {   // merge 256 -> 16
                unsigned long long kk[8];
#pragma unroll
                for (int j = 0; j < 8; j++) kk[j] = s_stk[lane + 32 * j];
                for (int r = 0; r < BB; r++) {
                    unsigned long long loc = kk[0];
#pragma unroll
                    for (int j = 1; j < 8; j++) if (kk[j] > loc) loc = kk[j];
                    for (int off = 16; off; off >>= 1) {
                        unsigned long long o = __shfl_xor_sync(0xffffffffu, loc, off);
                        if (o > loc) loc = o;
                    }
                    if (lane == r) g_part[blk * 16 + r] = loc;
#pragma unroll
                    for (int j = 0; j < 8; j++) if (kk[j] == loc) kk[j] = 0ULL;
                }
            }
        }
        gridbar();

        // ---- ph3: merge + select + LSTM GEMM (R10 verbatim) + elem + apply ----
        {
            {
                unsigned long long kk[4];
#pragma unroll
                for (int j = 0; j < 4; j++) kk[j] = g_part[wrp * 128 + lane + 32 * j];
                for (int r = 0; r < BB; r++) {
                    unsigned long long loc = kk[0];
#pragma unroll
                    for (int j = 1; j < 4; j++) if (kk[j] > loc) loc = kk[j];
                    for (int off = 16; off; off >>= 1) {
                        unsigned long long o = __shfl_xor_sync(0xffffffffu, loc, off);
                        if (o > loc) loc = o;
                    }
                    if (lane == r) s_stk[wrp * 16 + r] = loc;
#pragma unroll
                    for (int j = 0; j < 4; j++) if (kk[j] == loc) kk[j] = 0ULL;
                }
            }
            __syncthreads();
            if (wrp == 0) {
                unsigned long long kk[8];
#pragma unroll
                for (int j = 0; j < 8; j++) kk[j] = s_stk[lane + 32 * j];
                for (int r = 0; r < BB; r++) {
                    unsigned long long loc = kk[0];
#pragma unroll
                    for (int j = 1; j < 8; j++) if (kk[j] > loc) loc = kk[j];
                    for (int off = 16; off; off >>= 1) {
                        unsigned long long o = __shfl_xor_sync(0xffffffffu, loc, off);
                        if (o > loc) loc = o;
                    }
                    if (lane == r) {
                        s_nbsc[r] = unordf((unsigned)(loc >> 32));
                        unsigned id = 0xFFFFFFFFu - (unsigned)(loc & 0xFFFFFFFFu);
                        s_nbhypo[r] = (int)(id / (VV - 1));
                        s_nbtok[r]  = (int)(id % (VV - 1));
                    }
#pragma unroll
                    for (int j = 0; j < 8; j++) if (kk[j] == loc) kk[j] = 0ULL;
                }
                __syncwarp();
                float val = (lane < BB) ? (s_sc[lane] + s_blk[lane]) : s_nbsc[lane - BB];
                unsigned long long key = mkkey(val, (unsigned)lane);
                for (int r = 0; r < BB; r++) {
                    unsigned long long loc = key;
                    for (int off = 16; off; off >>= 1) {
                        unsigned long long o = __shfl_xor_sync(0xffffffffu, loc, off);
                        if (o > loc) loc = o;
                    }
                    unsigned idx = 0xFFFFFFFFu - (unsigned)(loc & 0xFFFFFFFFu);
                    if (lane == r) {
                        s_newsc[r] = unordf((unsigned)(loc >> 32));
                        s_isblank[r] = (idx < BB) ? 1 : 0;
                        s_bsel[r] = (idx < BB) ? (int)idx : (BB - 1);
                        int n2 = (int)idx - BB;
                        n2 = n2 < 0 ? 0 : (n2 > BB - 1 ? BB - 1 : n2);
                        s_nsel[r] = n2;
                    }
                    if (lane == (int)idx) key = 0ULL;
                }
            }
            __syncthreads();
            if (blk == 0 && tid < BB) g_scores2[np][tid] = s_newsc[tid];

            // LSTM GEMM: 16 chunks x 64k, Wx then Wh same acc, pipelined groups of 4
            const int quad = tid & 7, rgl = (tid >> 3) & 3, kc = tid >> 5;
            const int gate = quad >> 1, hf = quad & 1;
            const int gcol = gate * 1024 + blk * 8 + hf * 4;
            const unsigned long long* a0 = smp + (rgl * 4 + 0) * JP + kc * 64;
            const unsigned long long* a1 = a0 + JP;
            const unsigned long long* a2 = a1 + JP;
            const unsigned long long* a3 = a2 + JP;
            unsigned long long c00=0,c01=0,c10=0,c11=0,c20=0,c21=0,c30=0,c31=0;
#pragma unroll
            for (int j = 0; j < 8; j++) {
                int unit = j * NTHR + tid;
                int row = unit >> 8, k = (unit & 255) * 4;
                float4 v = *(const float4*)&embed[(size_t)s_nbtok[row] * HH + k];
                ulonglong2* dst = (ulonglong2*)(smp + row * JP + k);
                dst[0] = make_ulonglong2(pk2(v.x), pk2(v.y));
                dst[1] = make_ulonglong2(pk2(v.z), pk2(v.w));
            }
            __syncthreads();
            {
                const float* wb = Wx + (size_t)(kc * 64) * (4 * HH) + gcol;
                ulonglong2 wA[4], wB[4];
                LOADW(wA, wb, 4 * HH);
#pragma unroll 2
                for (int it = 0; it < 8; it++) {
                    LOADW(wB, wb, 4 * HH);
                    CONSUME(wA, it * 8);
                    if (it < 7) LOADW(wA, wb, 4 * HH);
                    CONSUME(wB, it * 8 + 4);
                }
            }
            __syncthreads();
            {
                const float* hs = g_h[par];
#pragma unroll
                for (int j = 0; j < 8; j++) {
                    int unit = j * NTHR + tid;
                    int row = unit >> 8, k = (unit & 255) * 4;
                    float4 v = *(const float4*)&hs[s_nbhypo[row] * HH + k];
                    ulonglong2* dst = (ulonglong2*)(smp + row * JP + k);
                    dst[0] = make_ulonglong2(pk2(v.x), pk2(v.y));
                    dst[1] = make_ulonglong2(pk2(v.z), pk2(v.w));
                }
            }
            __syncthreads();
            {
                const float* wb = Wh + (size_t)(kc * 64) * (4 * HH) + gcol;
                ulonglong2 wA[4], wB[4];
                LOADW(wA, wb, 4 * HH);
#pragma unroll 2
                for (int it = 0; it < 8; it++) {
                    LOADW(wB, wb, 4 * HH);
                    CONSUME(wA, it * 8);
                    if (it < 7) LOADW(wA, wb, 4 * HH);
                    CONSUME(wB, it * 8 + 4);
                }
            }
            __syncthreads();
            float* sred = (float*)smp;
            STORE_PARTIALS(sred, (kc * 32 + rgl * 8 + quad) * PS);
            __syncthreads();
            if (tid < 128) {
                int row = tid >> 3, quado = tid & 7;
                int rglo = row >> 2, r = row & 3;
                float s0 = 0.f, s1 = 0.f, s2 = 0.f, s3 = 0.f;
#pragma unroll
                for (int k16 = 0; k16 < 16; k16++) {
                    float4 f = *(const float4*)
                        &sred[(k16 * 32 + rglo * 8 + quado) * PS + r * 4];
                    s0 += f.x; s1 += f.y; s2 += f.z; s3 += f.w;
                }
                int gateo = quado >> 1;
                int u0 = (quado & 1) * 4;
                s_gates[row][gateo * 8 + u0 + 0] = s0 + blstm[gateo * 1024 + blk * 8 + u0 + 0];
                s_gates[row][gateo * 8 + u0 + 1] = s1 + blstm[gateo * 1024 + blk * 8 + u0 + 1];
                s_gates[row][gateo * 8 + u0 + 2] = s2 + blstm[gateo * 1024 + blk * 8 + u0 + 2];
                s_gates[row][gateo * 8 + u0 + 3] = s3 + blstm[gateo * 1024 + blk * 8 + u0 + 3];
            }
            __syncthreads();
            {
                int cell = tid >> 2, gsel = tid & 3;
                int j = cell >> 3, uo = cell & 7;
                float gval = s_gates[j][gsel * 8 + uo];
                s_act[cell][gsel] = (gsel == 2) ? tanh_acc(gval) : sigf(gval);
            }
            __syncthreads();
            if (tid < 128) {
                int j2 = tid >> 3, uo2 = tid & 7, u2 = blk * 8 + uo2;
                float cp = g_c[par][s_nbhypo[j2] * HH + u2];
                float cc = s_act[tid][1] * cp + s_act[tid][0] * s_act[tid][2];
                nc_s[j2][uo2] = cc;
                nh_s[j2][uo2] = s_act[tid][3] * tanh_acc(cc);
            }
            __syncthreads();
            if (tid < 128) {
                int i2 = tid >> 3, uo2 = tid & 7, u2 = blk * 8 + uo2;
                float hn, cn;
                if (s_isblank[i2]) {
                    hn = g_h[par][s_bsel[i2] * HH + u2];
                    cn = g_c[par][s_bsel[i2] * HH + u2];
                } else {
                    int ns = s_nsel[i2];
                    hn = nh_s[ns][uo2]; cn = nc_s[ns][uo2];
                }
                g_h[np][i2 * HH + u2] = hn;
                g_c[np][i2 * HH + u2] = cn;
            }
            if (tid < 64) {
                int i2 = tid >> 2, sl = blk * 4 + (tid & 3);
                int tok;
                if (s_isblank[i2]) {
                    tok = g_tokens[par][s_bsel[i2] * TT + sl];
                } else {
                    int ns = s_nsel[i2];
                    tok = (sl == t) ? s_nbtok[ns] : g_tokens[par][s_nbhypo[ns] * TT + sl];
                }
                g_tokens[np][i2 * TT + sl] = tok;
            }
        }
        gridbar();
    }

    // ================= epilogue =================
    if (blk == 0) {
        for (int e = tid; e < BB; e += NTHR) out[e] = g_scores2[0][e];
        for (int e = tid; e < BB * TT; e += NTHR) out[BB + e] = (float)g_tokens[0][e];
    }
}

// ---------------- host ----------------
extern "C" void kernel_launch(void* const* d_in, const int* in_sizes, int n_in,
                              void* d_out, int out_size) {
    const float* input   = (const float*)d_in[0];
    const float* enc_W   = (const float*)d_in[1];
    const float* enc_b   = (const float*)d_in[2];
    const float* embed   = (const float*)d_in[3];
    const float* Wx      = (const float*)d_in[4];
    const float* Wh      = (const float*)d_in[5];
    const float* b_lstm  = (const float*)d_in[6];
    const float* joint_W = (const float*)d_in[7];
    const float* joint_b = (const float*)d_in[8];
    (void)in_sizes; (void)n_in; (void)out_size;

    cudaFuncSetAttribute(rnnt_persist, cudaFuncAttributeMaxDynamicSharedMemorySize, DYN_SMEM);
    rnnt_persist<<<NBLK, NTHR, DYN_SMEM>>>(input, enc_W, enc_b, embed, Wx, Wh,
                                           b_lstm, joint_W, joint_b, (float*)d_out);
}

// round 15
// speedup vs baseline: 1.0317x; 1.0317x over previous
#include <cuda_runtime.h>
#include <math.h>
#include <stdint.h>

#define TT 512
#define DD 512
#define HH 1024
#define VV 8192
#define BB 16
#define BLANKTOK 8191
#define NEGF (-99999.0f)
#define EXPANDF 10.0f
#define NBLK 128
#define NTHR 512
#define JP 1026                       // packed-act row stride, u64 units (EVEN: 16B align)
#define PS 20                         // partial slot stride (floats), mod 4 == 0
#define DYN_SMEM (16 * JP * 8)        // 131328 bytes

// ---------------- device globals ----------------
__device__ __align__(16) float g_enc[TT * HH];
__device__ __align__(16) float g_pmax[BB * NBLK];
__device__ __align__(16) float g_pnb[BB * NBLK];
__device__ float g_mf[BB];
__device__ float g_blanklogit[BB];
__device__ __align__(16) double g_psum[BB * NBLK];
__device__ float g_scores2[2][BB];
__device__ __align__(16) float g_h[2][BB * HH];
__device__ __align__(16) float g_c[2][BB * HH];
__device__ int g_tokens[2][BB * TT];
__device__ unsigned long long g_part[NBLK * BB];
__device__ float g_g0[4 * HH];
__device__ unsigned g_bar_c1[8];            // per-group arrival counters (monotonic)
__device__ unsigned g_bar_c2;               // global group counter (monotonic)
__device__ volatile unsigned g_bar_gen;     // generation flag

// ---------------- helpers ----------------
__device__ __forceinline__ float sigf(float x) {
    return (float)(1.0 / (1.0 + exp(-(double)x)));
}
__device__ __forceinline__ float tanh_acc(float x) {
    return (float)tanh((double)x);
}
__device__ __forceinline__ unsigned ordf(float f) {
    unsigned u = __float_as_uint(f);
    return (u & 0x80000000u) ? ~u : (u | 0x80000000u);
}
__device__ __forceinline__ float unordf(unsigned s) {
    return (s & 0x80000000u) ? __uint_as_float(s & 0x7FFFFFFFu) : __uint_as_float(~s);
}
__device__ __forceinline__ unsigned long long mkkey(float v, unsigned idx) {
    return ((unsigned long long)ordf(v) << 32) | (unsigned long long)(0xFFFFFFFFu - idx);
}
__device__ __forceinline__ void ffma2(unsigned long long& d, unsigned long long a,
                                      unsigned long long b) {
    asm("fma.rn.f32x2 %0, %1, %2, %0;" : "+l"(d) : "l"(a), "l"(b));
}
__device__ __forceinline__ unsigned long long pk2(float x) {
    unsigned long long r;
    asm("mov.b64 %0, {%1, %1};" : "=l"(r) : "r"(__float_as_uint(x)));
    return r;
}
// two-level generation-tagged grid barrier: 8 group counters (16 blocks each),
// then one 8-way global counter. Monotonic counters, no resets -> race-free.
__device__ __forceinline__ void gridbar() {
    __syncthreads();
    if (threadIdx.x == 0) {
        __threadfence();
        unsigned gen = g_bar_gen;
        unsigned a = atomicAdd(&g_bar_c1[blockIdx.x >> 4], 1u);
        if (a == gen * 16u + 15u) {
            unsigned b = atomicAdd(&g_bar_c2, 1u);
            if (b == gen * 8u + 7u) {
                __threadfence();
                g_bar_gen = gen + 1u;
            } else {
                while (g_bar_gen == gen) { }
                __threadfence();
            }
        } else {
            while (g_bar_gen == gen) { }
            __threadfence();
        }
    }
    __syncthreads();
}

// ======== GEMM macros (identical to R10) ========
#define LOADW(W, PTR, STRIDE) do {                                          \
    _Pragma("unroll")                                                       \
    for (int _u = 0; _u < 4; _u++)                                          \
        W[_u] = *(const ulonglong2*)((PTR) + (size_t)_u * (STRIDE));        \
    (PTR) += (size_t)4 * (STRIDE);                                          \
} while (0)

#define CONSUME(W, KOFF) do {                                               \
    ulonglong2 xa = *(const ulonglong2*)(a0 + (KOFF));                      \
    ulonglong2 xb = *(const ulonglong2*)(a1 + (KOFF));                      \
    ulonglong2 xc = *(const ulonglong2*)(a2 + (KOFF));                      \
    ulonglong2 xd = *(const ulonglong2*)(a3 + (KOFF));                      \
    ffma2(c00, xa.x, W[0].x); ffma2(c01, xa.x, W[0].y);                     \
    ffma2(c10, xb.x, W[0].x); ffma2(c11, xb.x, W[0].y);                     \
    ffma2(c20, xc.x, W[0].x); ffma2(c21, xc.x, W[0].y);                     \
    ffma2(c30, xd.x, W[0].x); ffma2(c31, xd.x, W[0].y);                     \
    ffma2(c00, xa.y, W[1].x); ffma2(c01, xa.y, W[1].y);                     \
    ffma2(c10, xb.y, W[1].x); ffma2(c11, xb.y, W[1].y);                     \
    ffma2(c20, xc.y, W[1].x); ffma2(c21, xc.y, W[1].y);                     \
    ffma2(c30, xd.y, W[1].x); ffma2(c31, xd.y, W[1].y);                     \
    ulonglong2 ya = *(const ulonglong2*)(a0 + (KOFF) + 2);                  \
    ulonglong2 yb = *(const ulonglong2*)(a1 + (KOFF) + 2);                  \
    ulonglong2 yc = *(const ulonglong2*)(a2 + (KOFF) + 2);                  \
    ulonglong2 yd = *(const ulonglong2*)(a3 + (KOFF) + 2);                  \
    ffma2(c00, ya.x, W[2].x); ffma2(c01, ya.x, W[2].y);                     \
    ffma2(c10, yb.x, W[2].x); ffma2(c11, yb.x, W[2].y);                     \
    ffma2(c20, yc.x, W[2].x); ffma2(c21, yc.x, W[2].y);                     \
    ffma2(c30, yd.x, W[2].x); ffma2(c31, yd.x, W[2].y);                     \
    ffma2(c00, ya.y, W[3].x); ffma2(c01, ya.y, W[3].y);                     \
    ffma2(c10, yb.y, W[3].x); ffma2(c11, yb.y, W[3].y);                     \
    ffma2(c20, yc.y, W[3].x); ffma2(c21, yc.y, W[3].y);                     \
    ffma2(c30, yd.y, W[3].x); ffma2(c31, yd.y, W[3].y);                     \
} while (0)

#define STORE_PARTIALS(SRED, BASE) do {                                     \
    *(ulonglong2*)&(SRED)[(BASE) + 0]  = make_ulonglong2(c00, c01);         \
    *(ulonglong2*)&(SRED)[(BASE) + 4]  = make_ulonglong2(c10, c11);         \
    *(ulonglong2*)&(SRED)[(BASE) + 8]  = make_ulonglong2(c20, c21);         \
    *(ulonglong2*)&(SRED)[(BASE) + 12] = make_ulonglong2(c30, c31);         \
} while (0)

// ---------------- persistent kernel ----------------
__global__ void __launch_bounds__(NTHR, 1)
rnnt_persist(const float* __restrict__ inp,  const float* __restrict__ encW,
             const float* __restrict__ encb, const float* __restrict__ embed,
             const float* __restrict__ Wx,   const float* __restrict__ Wh,
             const float* __restrict__ blstm,const float* __restrict__ jW,
             const float* __restrict__ jb,   float* __restrict__ out) {
    extern __shared__ unsigned long long smp[];

    __shared__ float xr[DD];
    __shared__ float s_logits[BB][65];
    __shared__ float s_gates[BB][33];
    __shared__ float s_m[BB], s_nbm[BB], s_lz[BB], s_thr[BB], s_blk[BB], s_sc[BB];
    __shared__ double s_Z[BB];
    __shared__ float s_nbsc[BB], s_newsc[BB];
    __shared__ int s_nbhypo[BB], s_nbtok[BB], s_isblank[BB], s_bsel[BB], s_nsel[BB];
    __shared__ unsigned long long s_stk[256];
    __shared__ float s_act[128][4];
    __shared__ float nh_s[BB][8], nc_s[BB][8];

    const int tid = threadIdx.x;
    const int blk = blockIdx.x;
    const int lane = tid & 31;
    const int wrp = tid >> 5;   // 0..15 = beam row for per-beam phases

    // ================= prologue =================
    for (int t0 = blk; t0 < TT; t0 += NBLK) {
        for (int i = tid; i < DD; i += NTHR) xr[i] = inp[t0 * DD + i];
        __syncthreads();
        int col = tid * 2;
        float a0 = 0.f, a1 = 0.f;
#pragma unroll 4
        for (int k = 0; k < DD; k++) {
            float2 w = *(const float2*)&encW[(size_t)k * HH + col];
            a0 += xr[k] * w.x; a1 += xr[k] * w.y;
        }
        g_enc[(size_t)t0 * HH + col]     = a0 + encb[col];
        g_enc[(size_t)t0 * HH + col + 1] = a1 + encb[col + 1];
        __syncthreads();
    }
    gridbar();
    if (blk < 8) {
        int col = blk * NTHR + tid;
        float acc = 0.f;
        const float* er = &embed[(size_t)BLANKTOK * HH];
#pragma unroll 4
        for (int k = 0; k < HH; k++) acc += er[k] * Wx[(size_t)k * 4 * HH + col];
        g_g0[col] = acc + blstm[col];
    } else if (blk < 24) {
        int e = (blk - 8) * NTHR + tid;
        g_tokens[0][e] = BLANKTOK;
    } else if (blk == 24 && tid < BB) {
        g_scores2[0][tid] = (tid == 0) ? 0.f : -1000000000.0f;
    }
    gridbar();
    if (blk < 2) {
        int u = blk * NTHR + tid;
        float gi = g_g0[u], gg = g_g0[2 * HH + u], go = g_g0[3 * HH + u];
        float c0 = sigf(gi) * tanh_acc(gg);
        float h0 = sigf(go) * tanh_acc(c0);
        for (int b = 0; b < BB; b++) {
            g_h[0][b * HH + u] = h0;
            g_c[0][b * HH + u] = c0;
        }
    }
    gridbar();

    // ================= main loop =================
    for (int t = 0; t < TT; t++) {
        const int par = t & 1, np = par ^ 1;

        // ---- ph1: joint GEMM (pipelined, chunks 8x128) + logits + local stats ----
        {
            const float* hs = g_h[par];
            const float* et = &g_enc[(size_t)t * HH];
#pragma unroll
            for (int j = 0; j < 8; j++) {
                int unit = j * NTHR + tid;
                int row = unit >> 8, k = (unit & 255) * 4;
                float4 ev = *(const float4*)&et[k];
                float4 hv = *(const float4*)&hs[row * HH + k];
                float v0 = ev.x + hv.x; v0 = v0 > 0.f ? v0 : 0.f;
                float v1 = ev.y + hv.y; v1 = v1 > 0.f ? v1 : 0.f;
                float v2 = ev.z + hv.z; v2 = v2 > 0.f ? v2 : 0.f;
                float v3 = ev.w + hv.w; v3 = v3 > 0.f ? v3 : 0.f;
                ulonglong2* dst = (ulonglong2*)(smp + row * JP + k);
                dst[0] = make_ulonglong2(pk2(v0), pk2(v1));
                dst[1] = make_ulonglong2(pk2(v2), pk2(v3));
            }
            __syncthreads();
            const int quad = tid & 15, rg = (tid >> 4) & 3, kc = tid >> 6;
            const int col = blk * 64 + quad * 4;
            const float* wb = jW + (size_t)(kc * 128) * VV + col;
            const unsigned long long* a0 = smp + (rg * 4 + 0) * JP + kc * 128;
            const unsigned long long* a1 = a0 + JP;
            const unsigned long long* a2 = a1 + JP;
            const unsigned long long* a3 = a2 + JP;
            unsigned long long c00=0,c01=0,c10=0,c11=0,c20=0,c21=0,c30=0,c31=0;
            ulonglong2 wA[4], wB[4];
            LOADW(wA, wb, VV);
#pragma unroll 2
            for (int it = 0; it < 16; it++) {
                LOADW(wB, wb, VV);
                CONSUME(wA, it * 8);
                if (it < 15) LOADW(wA, wb, VV);
                CONSUME(wB, it * 8 + 4);
            }
            __syncthreads();
            float* sred = (float*)smp;
            STORE_PARTIALS(sred, (kc * 64 + rg * 16 + quad) * PS);
            __syncthreads();
            if (tid < 256) {
                int row = tid >> 4, quado = tid & 15;
                int rgo = row >> 2, r = row & 3;
                float s0 = 0.f, s1 = 0.f, s2 = 0.f, s3 = 0.f;
#pragma unroll
                for (int k8 = 0; k8 < 8; k8++) {
                    float4 f = *(const float4*)
                        &sred[(k8 * 64 + rgo * 16 + quado) * PS + r * 4];
                    s0 += f.x; s1 += f.y; s2 += f.z; s3 += f.w;
                }
                int c64 = quado * 4;
                s_logits[row][c64 + 0] = s0 + jb[blk * 64 + c64 + 0];
                s_logits[row][c64 + 1] = s1 + jb[blk * 64 + c64 + 1];
                s_logits[row][c64 + 2] = s2 + jb[blk * 64 + c64 + 2];
                s_logits[row][c64 + 3] = s3 + jb[blk * 64 + c64 + 3];
            }
            __syncthreads();
            float x0 = s_logits[wrp][lane], x1 = s_logits[wrp][lane + 32];
            float pm = fmaxf(x0, x1);
            float nb0 = (blk == 0 && lane < 4) ? -1e30f : x0;
            float nb1 = (blk == NBLK - 1 && lane == 31) ? -1e30f : x1;
            float pn = fmaxf(nb0, nb1);
            for (int off = 16; off; off >>= 1) {
                pm = fmaxf(pm, __shfl_xor_sync(0xffffffffu, pm, off));
                pn = fmaxf(pn, __shfl_xor_sync(0xffffffffu, pn, off));
            }
            double d = (double)expf(x0 - pm) + (double)expf(x1 - pm);
            for (int off = 16; off; off >>= 1)
                d += __shfl_down_sync(0xffffffffu, d, off);
            if (lane == 0) {
                g_pmax[wrp * NBLK + blk] = pm;
                g_pnb[wrp * NBLK + blk]  = pn;
                g_psum[wrp * NBLK + blk] = d;
                if (blk == 0)
                    g_mf[wrp] = fmaxf(fmaxf(s_logits[wrp][0], s_logits[wrp][1]),
                                      fmaxf(s_logits[wrp][2], s_logits[wrp][3]));
                if (blk == NBLK - 1) g_blanklogit[wrp] = s_logits[wrp][63];
            }
        }
        gridbar();

        // ---- ph2: combine stats (lane-packed FP64 log) + candidates + block top-16 ----
        {
            const float* pma = &g_pmax[wrp * NBLK];
            const float* pna = &g_pnb[wrp * NBLK];
            const double* psa = &g_psum[wrp * NBLK];
            float pa0 = pma[lane * 4 + 0], pa1 = pma[lane * 4 + 1];
            float pa2 = pma[lane * 4 + 2], pa3 = pma[lane * 4 + 3];
            float pm = fmaxf(fmaxf(pa0, pa1), fmaxf(pa2, pa3));
            float q0 = pna[lane * 4 + 0], q1 = pna[lane * 4 + 1];
            float q2 = pna[lane * 4 + 2], q3 = pna[lane * 4 + 3];
            float pn = fmaxf(fmaxf(q0, q1), fmaxf(q2, q3));
            for (int off = 16; off; off >>= 1) {
                pm = fmaxf(pm, __shfl_xor_sync(0xffffffffu, pm, off));
                pn = fmaxf(pn, __shfl_xor_sync(0xffffffffu, pn, off));
            }
            double Z = psa[lane * 4 + 0] * (double)expf(pa0 - pm)
                     + psa[lane * 4 + 1] * (double)expf(pa1 - pm)
                     + psa[lane * 4 + 2] * (double)expf(pa2 - pm)
                     + psa[lane * 4 + 3] * (double)expf(pa3 - pm);
            for (int off = 16; off; off >>= 1)
                Z += __shfl_xor_sync(0xffffffffu, Z, off);
            if (lane == 0) {
                s_m[wrp] = pm;
                s_nbm[wrp] = pn;
                s_Z[wrp] = Z;
                s_sc[wrp] = g_scores2[par][wrp];
            }
            __syncthreads();
            if (wrp == 0 && lane < BB) {
                float m = s_m[lane];
                float lz = (float)log(s_Z[lane]);
                s_lz[lane] = lz;
                float t1 = (s_nbm[lane] - m) - lz;
                float t2 = ((g_mf[lane] - m) - lz) + NEGF;
                s_thr[lane] = fmaxf(t1, t2) - EXPANDF;
                s_blk[lane] = (g_blanklogit[lane] - m) - lz;
            }
            __syncthreads();
            float m = s_m[wrp], lz = s_lz[wrp], thr = s_thr[wrp], sc = s_sc[wrp];
            int c0 = lane, c1 = lane + 32;
            float x0 = s_logits[wrp][c0], x1 = s_logits[wrp][c1];
            float lp0 = (x0 - m) - lz;
            if (blk == 0 && c0 < 4) lp0 += NEGF;
            float lp1 = (x1 - m) - lz;
            float nb0 = lp0 > thr ? lp0 : NEGF;
            float nb1 = lp1 > thr ? lp1 : NEGF;
            int v0 = blk * 64 + c0, v1 = blk * 64 + c1;
            unsigned long long k0 = mkkey(sc + nb0, (unsigned)(wrp * (VV - 1) + v0));
            unsigned long long k1 = (v1 == VV - 1) ? 0ULL
                                  : mkkey(sc + nb1, (unsigned)(wrp * (VV - 1) + v1));
            for (int r = 0; r < BB; r++) {
                unsigned long long loc = k0 > k1 ? k0 : k1;
                for (int off = 16; off; off >>= 1) {
                    unsigned long long o = __shfl_xor_sync(0xffffffffu, loc, off);
                    if (o > loc) loc = o;
                }
                if (lane == r) s_stk[wrp * 16 + r] = loc;
                if (k0 == loc) k0 = 0ULL;
                if (k1 == loc) k1 = 0ULL;
            }
            __syncthreads();
            if (wrp == 0) {   // merge 256 -> 16
                unsigned long long kk[8];
#pragma unroll
                for (int j = 0; j < 8; j++) kk[j] = s_stk[lane + 32 * j];
                for (int r = 0; r < BB; r++) {
                    unsigned long long loc = kk[0];
#pragma unroll
                    for (int j = 1; j < 8; j++) if (kk[j] > loc) loc = kk[j];
                    for (int off = 16; off; off >>= 1) {
                        unsigned long long o = __shfl_xor_sync(0xffffffffu, loc, off);
                        if (o > loc) loc = o;
                    }
                    if (lane == r) g_part[blk * 16 + r] = loc;
#pragma unroll
                    for (int j = 0; j < 8; j++) if (kk[j] == loc) kk[j] = 0ULL;
                }
            }
        }
        gridbar();

        // ---- ph3: merge + select + LSTM GEMM (pipelined) + elem + apply ----
        {
            {
                unsigned long long kk[4];
#pragma unroll
                for (int j = 0; j < 4; j++) kk[j] = g_part[wrp * 128 + lane + 32 * j];
                for (int r = 0; r < BB; r++) {
                    unsigned long long loc = kk[0];
#pragma unroll
                    for (int j = 1; j < 4; j++) if (kk[j] > loc) loc = kk[j];
                    for (int off = 16; off; off >>= 1) {
                        unsigned long long o = __shfl_xor_sync(0xffffffffu, loc, off);
                        if (o > loc) loc = o;
                    }
                    if (lane == r) s_stk[wrp * 16 + r] = loc;
#pragma unroll
                    for (int j = 0; j < 4; j++) if (kk[j] == loc) kk[j] = 0ULL;
                }
            }
            __syncthreads();
            if (wrp == 0) {
                unsigned long long kk[8];
#pragma unroll
                for (int j = 0; j < 8; j++) kk[j] = s_stk[lane + 32 * j];
                for (int r = 0; r < BB; r++) {
                    unsigned long long loc = kk[0];
#pragma unroll
                    for (int j = 1; j < 8; j++) if (kk[j] > loc) loc = kk[j];
                    for (int off = 16; off; off >>= 1) {
                        unsigned long long o = __shfl_xor_sync(0xffffffffu, loc, off);
                        if (o > loc) loc = o;
                    }
                    if (lane == r) {
                        s_nbsc[r] = unordf((unsigned)(loc >> 32));
                        unsigned id = 0xFFFFFFFFu - (unsigned)(loc & 0xFFFFFFFFu);
                        s_nbhypo[r] = (int)(id / (VV - 1));
                        s_nbtok[r]  = (int)(id % (VV - 1));
                    }
#pragma unroll
                    for (int j = 0; j < 8; j++) if (kk[j] == loc) kk[j] = 0ULL;
                }
                __syncwarp();
                float val = (lane < BB) ? (s_sc[lane] + s_blk[lane]) : s_nbsc[lane - BB];
                unsigned long long key = mkkey(val, (unsigned)lane);
                for (int r = 0; r < BB; r++) {
                    unsigned long long loc = key;
                    for (int off = 16; off; off >>= 1) {
                        unsigned long long o = __shfl_xor_sync(0xffffffffu, loc, off);
                        if (o > loc) loc = o;
                    }
                    unsigned idx = 0xFFFFFFFFu - (unsigned)(loc & 0xFFFFFFFFu);
                    if (lane == r) {
                        s_newsc[r] = unordf((unsigned)(loc >> 32));
                        s_isblank[r] = (idx < BB) ? 1 : 0;
                        s_bsel[r] = (idx < BB) ? (int)idx : (BB - 1);
                        int n2 = (int)idx - BB;
                        n2 = n2 < 0 ? 0 : (n2 > BB - 1 ? BB - 1 : n2);
                        s_nsel[r] = n2;
                    }
                    if (lane == (int)idx) key = 0ULL;
                }
            }
            __syncthreads();
            if (blk == 0 && tid < BB) g_scores2[np][tid] = s_newsc[tid];

            // LSTM GEMM: 16 chunks x 64k, Wx then Wh same acc, pipelined groups of 4
            const int quad = tid & 7, rgl = (tid >> 3) & 3, kc = tid >> 5;
            const int gate = quad >> 1, hf = quad & 1;
            const int gcol = gate * 1024 + blk * 8 + hf * 4;
            const unsigned long long* a0 = smp + (rgl * 4 + 0) * JP + kc * 64;
            const unsigned long long* a1 = a0 + JP;
            const unsigned long long* a2 = a1 + JP;
            const unsigned long long* a3 = a2 + JP;
            unsigned long long c00=0,c01=0,c10=0,c11=0,c20=0,c21=0,c30=0,c31=0;
#pragma unroll
            for (int j = 0; j < 8; j++) {
                int unit = j * NTHR + tid;
                int row = unit >> 8, k = (unit & 255) * 4;
                float4 v = *(const float4*)&embed[(size_t)s_nbtok[row] * HH + k];
                ulonglong2* dst = (ulonglong2*)(smp + row * JP + k);
                dst[0] = make_ulonglong2(pk2(v.x), pk2(v.y));
                dst[1] = make_ulonglong2(pk2(v.z), pk2(v.w));
            }
            __syncthreads();
            {
                const float* wb = Wx + (size_t)(kc * 64) * (4 * HH) + gcol;
                ulonglong2 wA[4], wB[4];
                LOADW(wA, wb, 4 * HH);
#pragma unroll 2
                for (int it = 0; it < 8; it++) {
                    LOADW(wB, wb, 4 * HH);
                    CONSUME(wA, it * 8);
                    if (it < 7) LOADW(wA, wb, 4 * HH);
                    CONSUME(wB, it * 8 + 4);
                }
            }
            __syncthreads();
            {
                const float* hs = g_h[par];
#pragma unroll
                for (int j = 0; j < 8; j++) {
                    int unit = j * NTHR + tid;
                    int row = unit >> 8, k = (unit & 255) * 4;
                    float4 v = *(const float4*)&hs[s_nbhypo[row] * HH + k];
                    ulonglong2* dst = (ulonglong2*)(smp + row * JP + k);
                    dst[0] = make_ulonglong2(pk2(v.x), pk2(v.y));
                    dst[1] = make_ulonglong2(pk2(v.z), pk2(v.w));
                }
            }
            __syncthreads();
            {
                const float* wb = Wh + (size_t)(kc * 64) * (4 * HH) + gcol;
                ulonglong2 wA[4], wB[4];
                LOADW(wA, wb, 4 * HH);
#pragma unroll 2
                for (int it = 0; it < 8; it++) {
                    LOADW(wB, wb, 4 * HH);
                    CONSUME(wA, it * 8);
                    if (it < 7) LOADW(wA, wb, 4 * HH);
                    CONSUME(wB, it * 8 + 4);
                }
            }
            __syncthreads();
            float* sred = (float*)smp;
            STORE_PARTIALS(sred, (kc * 32 + rgl * 8 + quad) * PS);
            __syncthreads();
            if (tid < 128) {
                int row = tid >> 3, quado = tid & 7;
                int rglo = row >> 2, r = row & 3;
                float s0 = 0.f, s1 = 0.f, s2 = 0.f, s3 = 0.f;
#pragma unroll
                for (int k16 = 0; k16 < 16; k16++) {
                    float4 f = *(const float4*)
                        &sred[(k16 * 32 + rglo * 8 + quado) * PS + r * 4];
                    s0 += f.x; s1 += f.y; s2 += f.z; s3 += f.w;
                }
                int gateo = quado >> 1;
                int u0 = (quado & 1) * 4;
                s_gates[row][gateo * 8 + u0 + 0] = s0 + blstm[gateo * 1024 + blk * 8 + u0 + 0];
                s_gates[row][gateo * 8 + u0 + 1] = s1 + blstm[gateo * 1024 + blk * 8 + u0 + 1];
                s_gates[row][gateo * 8 + u0 + 2] = s2 + blstm[gateo * 1024 + blk * 8 + u0 + 2];
                s_gates[row][gateo * 8 + u0 + 3] = s3 + blstm[gateo * 1024 + blk * 8 + u0 + 3];
            }
            __syncthreads();
            {
                int cell = tid >> 2, gsel = tid & 3;
                int j = cell >> 3, uo = cell & 7;
                float gval = s_gates[j][gsel * 8 + uo];
                s_act[cell][gsel] = (gsel == 2) ? tanh_acc(gval) : sigf(gval);
            }
            __syncthreads();
            if (tid < 128) {
                int j2 = tid >> 3, uo2 = tid & 7, u2 = blk * 8 + uo2;
                float cp = g_c[par][s_nbhypo[j2] * HH + u2];
                float cc = s_act[tid][1] * cp + s_act[tid][0] * s_act[tid][2];
                nc_s[j2][uo2] = cc;
                nh_s[j2][uo2] = s_act[tid][3] * tanh_acc(cc);
            }
            __syncthreads();
            if (tid < 128) {
                int i2 = tid >> 3, uo2 = tid & 7, u2 = blk * 8 + uo2;
                float hn, cn;
                if (s_isblank[i2]) {
                    hn = g_h[par][s_bsel[i2] * HH + u2];
                    cn = g_c[par][s_bsel[i2] * HH + u2];
                } else {
                    int ns = s_nsel[i2];
                    hn = nh_s[ns][uo2]; cn = nc_s[ns][uo2];
                }
                g_h[np][i2 * HH + u2] = hn;
                g_c[np][i2 * HH + u2] = cn;
            }
            if (tid < 64) {
                int i2 = tid >> 2, sl = blk * 4 + (tid & 3);
                int tok;
                if (s_isblank[i2]) {
                    tok = g_tokens[par][s_bsel[i2] * TT + sl];
                } else {
                    int ns = s_nsel[i2];
                    tok = (sl == t) ? s_nbtok[ns] : g_tokens[par][s_nbhypo[ns] * TT + sl];
                }
                g_tokens[np][i2 * TT + sl] = tok;
            }
        }
        gridbar();
    }

    // ================= epilogue =================
    if (blk == 0) {
        for (int e = tid; e < BB; e += NTHR) out[e] = g_scores2[0][e];
        for (int e = tid; e < BB * TT; e += NTHR) out[BB + e] = (float)g_tokens[0][e];
    }
}

// ---------------- host ----------------
extern "C" void kernel_launch(void* const* d_in, const int* in_sizes, int n_in,
                              void* d_out, int out_size) {
    const float* input   = (const float*)d_in[0];
    const float* enc_W   = (const float*)d_in[1];
    const float* enc_b   = (const float*)d_in[2];
    const float* embed   = (const float*)d_in[3];
    const float* Wx      = (const float*)d_in[4];
    const float* Wh      = (const float*)d_in[5];
    const float* b_lstm  = (const float*)d_in[6];
    const float* joint_W = (const float*)d_in[7];
    const float* joint_b = (const float*)d_in[8];
    (void)in_sizes; (void)n_in; (void)out_size;

    cudaFuncSetAttribute(rnnt_persist, cudaFuncAttributeMaxDynamicSharedMemorySize, DYN_SMEM);
    rnnt_persist<<<NBLK, NTHR, DYN_SMEM>>>(input, enc_W, enc_b, embed, Wx, Wh,
                                           b_lstm, joint_W, joint_b, (float*)d_out);
}

// round 16
// speedup vs baseline: 1.1999x; 1.1630x over previous
#include <cuda_runtime.h>
#include <math.h>
#include <stdint.h>

#define TT 512
#define DD 512
#define HH 1024
#define VV 8192
#define BB 16
#define BLANKTOK 8191
#define NEGF (-99999.0f)
#define EXPANDF 10.0f
#define NBLK 128
#define NTHR 512
#define JP 1026                       // packed-act row stride, u64 units
#define PS 20                        // partial slot stride (floats), mod 4 == 0
#define WOFFU (16 * JP)              // u64 offset of per-warp weight windows
#define DYN_SMEM (16 * JP * 8 + 65536)   // 131328 + 64KB = 196864 bytes

// ---------------- device globals ----------------
__device__ __align__(16) float g_enc[TT * HH];
__device__ __align__(16) float g_pmax[BB * NBLK];
__device__ __align__(16) float g_pnb[BB * NBLK];
__device__ float g_mf[BB];
__device__ float g_blanklogit[BB];
__device__ __align__(16) double g_psum[BB * NBLK];
__device__ float g_scores2[2][BB];
__device__ __align__(16) float g_h[2][BB * HH];
__device__ __align__(16) float g_c[2][BB * HH];
__device__ int g_tokens[2][BB * TT];
__device__ unsigned long long g_part[NBLK * BB];
__device__ float g_g0[4 * HH];
__device__ unsigned g_bar_gen;
__device__ unsigned g_bar_cnt;

// ---------------- helpers ----------------
__device__ __forceinline__ float sigf(float x) {
    return (float)(1.0 / (1.0 + exp(-(double)x)));
}
__device__ __forceinline__ float tanh_acc(float x) {
    return (float)tanh((double)x);
}
__device__ __forceinline__ unsigned ordf(float f) {
    unsigned u = __float_as_uint(f);
    return (u & 0x80000000u) ? ~u : (u | 0x80000000u);
}
__device__ __forceinline__ float unordf(unsigned s) {
    return (s & 0x80000000u) ? __uint_as_float(s & 0x7FFFFFFFu) : __uint_as_float(~s);
}
__device__ __forceinline__ unsigned long long mkkey(float v, unsigned idx) {
    return ((unsigned long long)ordf(v) << 32) | (unsigned long long)(0xFFFFFFFFu - idx);
}
__device__ __forceinline__ void ffma2(unsigned long long& d, unsigned long long a,
                                      unsigned long long b) {
    asm("fma.rn.f32x2 %0, %1, %2, %0;" : "+l"(d) : "l"(a), "l"(b));
}
__device__ __forceinline__ unsigned long long pk2(float x) {
    unsigned long long r;
    asm("mov.b64 %0, {%1, %1};" : "=l"(r) : "r"(__float_as_uint(x)));
    return r;
}
// R10 single-counter grid barrier (two-level variant measured slower in R15)
__device__ __forceinline__ void gridbar() {
    __syncthreads();
    if (threadIdx.x == 0) {
        __threadfence();
        unsigned gen = *(volatile unsigned*)&g_bar_gen;
        unsigned a = atomicAdd(&g_bar_cnt, 1u);
        if (a == NBLK - 1u) {
            g_bar_cnt = 0u;
            __threadfence();
            *(volatile unsigned*)&g_bar_gen = gen + 1u;
        } else {
            while (*(volatile unsigned*)&g_bar_gen == gen) { }
            __threadfence();
        }
    }
    __syncthreads();
}
// cp.async helpers
__device__ __forceinline__ void cpa16(unsigned dst, const void* src) {
    asm volatile("cp.async.cg.shared.global [%0], [%1], 16;" :: "r"(dst), "l"(src));
}
template <int N>
__device__ __forceinline__ void cpwait() {
    asm volatile("cp.async.wait_group %0;" :: "n"(N));
}
#define CP_COMMIT() asm volatile("cp.async.commit_group;")

// consume 4 k's with weights in W[0..3]; FMA order identical to R10 (bit-exact)
#define CONSUME(W, KOFF) do {                                               \
    ulonglong2 xa = *(const ulonglong2*)(a0 + (KOFF));                      \
    ulonglong2 xb = *(const ulonglong2*)(a1 + (KOFF));                      \
    ulonglong2 xc = *(const ulonglong2*)(a2 + (KOFF));                      \
    ulonglong2 xd = *(const ulonglong2*)(a3 + (KOFF));                      \
    ffma2(c00, xa.x, W[0].x); ffma2(c01, xa.x, W[0].y);                     \
    ffma2(c10, xb.x, W[0].x); ffma2(c11, xb.x, W[0].y);                     \
    ffma2(c20, xc.x, W[0].x); ffma2(c21, xc.x, W[0].y);                     \
    ffma2(c30, xd.x, W[0].x); ffma2(c31, xd.x, W[0].y);                     \
    ffma2(c00, xa.y, W[1].x); ffma2(c01, xa.y, W[1].y);                     \
    ffma2(c10, xb.y, W[1].x); ffma2(c11, xb.y, W[1].y);                     \
    ffma2(c20, xc.y, W[1].x); ffma2(c21, xc.y, W[1].y);                     \
    ffma2(c30, xd.y, W[1].x); ffma2(c31, xd.y, W[1].y);                     \
    ulonglong2 ya = *(const ulonglong2*)(a0 + (KOFF) + 2);                  \
    ulonglong2 yb = *(const ulonglong2*)(a1 + (KOFF) + 2);                  \
    ulonglong2 yc = *(const ulonglong2*)(a2 + (KOFF) + 2);                  \
    ulonglong2 yd = *(const ulonglong2*)(a3 + (KOFF) + 2);                  \
    ffma2(c00, ya.x, W[2].x); ffma2(c01, ya.x, W[2].y);                     \
    ffma2(c10, yb.x, W[2].x); ffma2(c11, yb.x, W[2].y);                     \
    ffma2(c20, yc.x, W[2].x); ffma2(c21, yc.x, W[2].y);                     \
    ffma2(c30, yd.x, W[2].x); ffma2(c31, yd.x, W[2].y);                     \
    ffma2(c00, ya.y, W[3].x); ffma2(c01, ya.y, W[3].y);                     \
    ffma2(c10, yb.y, W[3].x); ffma2(c11, yb.y, W[3].y);                     \
    ffma2(c20, yc.y, W[3].x); ffma2(c21, yc.y, W[3].y);                     \
    ffma2(c30, yd.y, W[3].x); ffma2(c31, yd.y, W[3].y);                     \
} while (0)

#define STORE_PARTIALS(SRED, BASE) do {                                     \
    *(ulonglong2*)&(SRED)[(BASE) + 0]  = make_ulonglong2(c00, c01);         \
    *(ulonglong2*)&(SRED)[(BASE) + 4]  = make_ulonglong2(c10, c11);         \
    *(ulonglong2*)&(SRED)[(BASE) + 8]  = make_ulonglong2(c20, c21);         \
    *(ulonglong2*)&(SRED)[(BASE) + 12] = make_ulonglong2(c30, c31);         \
} while (0)

// joint: warp-private weight stage fill (1KB/stage, 2 cpa16 per lane)
#define JFILL(S) do {                                                        \
    unsigned _db = jwb + (unsigned)(((S) & 3) * 1024);                       \
    _Pragma("unroll")                                                        \
    for (int _j = 0; _j < 2; _j++) {                                         \
        int _seg = lane + 32 * _j;                                           \
        int _row = _seg >> 4, _c4 = _seg & 15;                               \
        const float* _src = jW + (size_t)(kc * 128 + (S) * 4 + _row) * VV    \
                          + blk * 64 + _c4 * 4;                              \
        cpa16(_db + (unsigned)(_seg * 16), _src);                            \
    }                                                                        \
    CP_COMMIT();                                                             \
} while (0)

// lstm: warp-private weight stage fill (512B/stage, 1 cpa16 per lane)
#define LFILL(WPTR, S) do {                                                  \
    unsigned _db = lwb + (unsigned)(((S) & 3) * 512);                        \
    int _u = lane >> 3, _sub = lane & 7, _g = _sub >> 1, _hf = _sub & 1;     \
    const float* _src = (WPTR) + (size_t)(kc * 64 + (S) * 4 + _u) * (4 * HH) \
                      + _g * 1024 + blk * 8 + _hf * 4;                       \
    cpa16(_db + (unsigned)(lane * 16), _src);                                \
    CP_COMMIT();                                                             \
} while (0)

// ---------------- persistent kernel ----------------
__global__ void __launch_bounds__(NTHR, 1)
rnnt_persist(const float* __restrict__ inp,  const float* __restrict__ encW,
             const float* __restrict__ encb, const float* __restrict__ embed,
             const float* __restrict__ Wx,   const float* __restrict__ Wh,
             const float* __restrict__ blstm,const float* __restrict__ jW,
             const float* __restrict__ jb,   float* __restrict__ out) {
    extern __shared__ unsigned long long smp[];

    __shared__ float xr[DD];
    __shared__ float s_logits[BB][65];
    __shared__ float s_gates[BB][33];
    __shared__ float s_m[BB], s_nbm[BB], s_lz[BB], s_thr[BB], s_blk[BB], s_sc[BB];
    __shared__ double s_Z[BB];
    __shared__ float s_nbsc[BB], s_newsc[BB];
    __shared__ int s_nbhypo[BB], s_nbtok[BB], s_isblank[BB], s_bsel[BB], s_nsel[BB];
    __shared__ unsigned long long s_stk[256];
    __shared__ float s_act[128][4];
    __shared__ float nh_s[BB][8], nc_s[BB][8];

    const int tid = threadIdx.x;
    const int blk = blockIdx.x;
    const int lane = tid & 31;
    const int wrp = tid >> 5;   // 0..15 = beam row for per-beam phases

    unsigned smem_u32;
    asm("{ .reg .u64 t; cvta.to.shared.u64 t, %1; cvt.u32.u64 %0, t; }"
        : "=r"(smem_u32) : "l"(smp));
    const unsigned jwb = smem_u32 + (unsigned)(WOFFU * 8) + (unsigned)(wrp * 4096);
    const unsigned lwb = smem_u32 + (unsigned)(WOFFU * 8) + (unsigned)(wrp * 2048);

    // ================= prologue =================
    for (int t0 = blk; t0 < TT; t0 += NBLK) {
        for (int i = tid; i < DD; i += NTHR) xr[i] = inp[t0 * DD + i];
        __syncthreads();
        int col = tid * 2;
        float a0 = 0.f, a1 = 0.f;
#pragma unroll 4
        for (int k = 0; k < DD; k++) {
            float2 w = *(const float2*)&encW[(size_t)k * HH + col];
            a0 += xr[k] * w.x; a1 += xr[k] * w.y;
        }
        g_enc[(size_t)t0 * HH + col]     = a0 + encb[col];
        g_enc[(size_t)t0 * HH + col + 1] = a1 + encb[col + 1];
        __syncthreads();
    }
    gridbar();
    if (blk < 8) {
        int col = blk * NTHR + tid;
        float acc = 0.f;
        const float* er = &embed[(size_t)BLANKTOK * HH];
#pragma unroll 4
        for (int k = 0; k < HH; k++) acc += er[k] * Wx[(size_t)k * 4 * HH + col];
        g_g0[col] = acc + blstm[col];
    } else if (blk < 24) {
        int e = (blk - 8) * NTHR + tid;
        g_tokens[0][e] = BLANKTOK;
    } else if (blk == 24 && tid < BB) {
        g_scores2[0][tid] = (tid == 0) ? 0.f : -1000000000.0f;
    }
    gridbar();
    if (blk < 2) {
        int u = blk * NTHR + tid;
        float gi = g_g0[u], gg = g_g0[2 * HH + u], go = g_g0[3 * HH + u];
        float c0 = sigf(gi) * tanh_acc(gg);
        float h0 = sigf(go) * tanh_acc(c0);
        for (int b = 0; b < BB; b++) {
            g_h[0][b * HH + u] = h0;
            g_c[0][b * HH + u] = c0;
        }
    }
    gridbar();

    // ================= main loop =================
    for (int t = 0; t < TT; t++) {
        const int par = t & 1, np = par ^ 1;

        // ---- ph1: joint GEMM (warp-private cp.async weight pipeline) ----
        {
            const int quad = tid & 15, rg = (tid >> 4) & 3, kc = tid >> 6;
            // prime 3 weight stages; latency overlaps the act fill
            JFILL(0); JFILL(1); JFILL(2);

            const float* hs = g_h[par];
            const float* et = &g_enc[(size_t)t * HH];
#pragma unroll
            for (int j = 0; j < 8; j++) {
                int unit = j * NTHR + tid;
                int row = unit >> 8, k = (unit & 255) * 4;
                float4 ev = *(const float4*)&et[k];
                float4 hv = *(const float4*)&hs[row * HH + k];
                float v0 = ev.x + hv.x; v0 = v0 > 0.f ? v0 : 0.f;
                float v1 = ev.y + hv.y; v1 = v1 > 0.f ? v1 : 0.f;
                float v2 = ev.z + hv.z; v2 = v2 > 0.f ? v2 : 0.f;
                float v3 = ev.w + hv.w; v3 = v3 > 0.f ? v3 : 0.f;
                ulonglong2* dst = (ulonglong2*)(smp + row * JP + k);
                dst[0] = make_ulonglong2(pk2(v0), pk2(v1));
                dst[1] = make_ulonglong2(pk2(v2), pk2(v3));
            }
            __syncthreads();
            const unsigned long long* a0 = smp + (rg * 4 + 0) * JP + kc * 128;
            const unsigned long long* a1 = a0 + JP;
            const unsigned long long* a2 = a1 + JP;
            const unsigned long long* a3 = a2 + JP;
            const unsigned long long* wwin = smp + WOFFU + wrp * 512;
            unsigned long long c00=0,c01=0,c10=0,c11=0,c20=0,c21=0,c30=0,c31=0;
#pragma unroll 1
            for (int s = 0; s < 32; s++) {
                if (s <= 29) cpwait<2>();
                else if (s == 30) cpwait<1>();
                else cpwait<0>();
                __syncwarp();
                const unsigned long long* wsl = wwin + (s & 3) * 128 + quad * 2;
                ulonglong2 W[4];
                W[0] = *(const ulonglong2*)(wsl +  0);
                W[1] = *(const ulonglong2*)(wsl + 32);
                W[2] = *(const ulonglong2*)(wsl + 64);
                W[3] = *(const ulonglong2*)(wsl + 96);
                CONSUME(W, s * 4);
                if (s < 29) JFILL(s + 3);
            }
            __syncthreads();
            float* sred = (float*)smp;
            STORE_PARTIALS(sred, (kc * 64 + rg * 16 + quad) * PS);
            __syncthreads();
            if (tid < 256) {
                int row = tid >> 4, quado = tid & 15;
                int rgo = row >> 2, r = row & 3;
                float s0 = 0.f, s1 = 0.f, s2 = 0.f, s3 = 0.f;
#pragma unroll
                for (int k8 = 0; k8 < 8; k8++) {
                    float4 f = *(const float4*)
                        &sred[(k8 * 64 + rgo * 16 + quado) * PS + r * 4];
                    s0 += f.x; s1 += f.y; s2 += f.z; s3 += f.w;
                }
                int c64 = quado * 4;
                s_logits[row][c64 + 0] = s0 + jb[blk * 64 + c64 + 0];
                s_logits[row][c64 + 1] = s1 + jb[blk * 64 + c64 + 1];
                s_logits[row][c64 + 2] = s2 + jb[blk * 64 + c64 + 2];
                s_logits[row][c64 + 3] = s3 + jb[blk * 64 + c64 + 3];
            }
            __syncthreads();
            float x0 = s_logits[wrp][lane], x1 = s_logits[wrp][lane + 32];
            float pm = fmaxf(x0, x1);
            float nb0 = (blk == 0 && lane < 4) ? -1e30f : x0;
            float nb1 = (blk == NBLK - 1 && lane == 31) ? -1e30f : x1;
            float pn = fmaxf(nb0, nb1);
            for (int off = 16; off; off >>= 1) {
                pm = fmaxf(pm, __shfl_xor_sync(0xffffffffu, pm, off));
                pn = fmaxf(pn, __shfl_xor_sync(0xffffffffu, pn, off));
            }
            double d = (double)expf(x0 - pm) + (double)expf(x1 - pm);
            for (int off = 16; off; off >>= 1)
                d += __shfl_down_sync(0xffffffffu, d, off);
            if (lane == 0) {
                g_pmax[wrp * NBLK + blk] = pm;
                g_pnb[wrp * NBLK + blk]  = pn;
                g_psum[wrp * NBLK + blk] = d;
                if (blk == 0)
                    g_mf[wrp] = fmaxf(fmaxf(s_logits[wrp][0], s_logits[wrp][1]),
                                      fmaxf(s_logits[wrp][2], s_logits[wrp][3]));
                if (blk == NBLK - 1) g_blanklogit[wrp] = s_logits[wrp][63];
            }
        }
        gridbar();

        // ---- ph2: combine stats + candidates + block top-16 (R10 verbatim) ----
        {
            const float* pma = &g_pmax[wrp * NBLK];
            const float* pna = &g_pnb[wrp * NBLK];
            const double* psa = &g_psum[wrp * NBLK];
            float pa0 = pma[lane * 4 + 0], pa1 = pma[lane * 4 + 1];
            float pa2 = pma[lane * 4 + 2], pa3 = pma[lane * 4 + 3];
            float pm = fmaxf(fmaxf(pa0, pa1), fmaxf(pa2, pa3));
            float q0 = pna[lane * 4 + 0], q1 = pna[lane * 4 + 1];
            float q2 = pna[lane * 4 + 2], q3 = pna[lane * 4 + 3];
            float pn = fmaxf(fmaxf(q0, q1), fmaxf(q2, q3));
            for (int off = 16; off; off >>= 1) {
                pm = fmaxf(pm, __shfl_xor_sync(0xffffffffu, pm, off));
                pn = fmaxf(pn, __shfl_xor_sync(0xffffffffu, pn, off));
            }
            double Z = psa[lane * 4 + 0] * (double)expf(pa0 - pm)
                     + psa[lane * 4 + 1] * (double)expf(pa1 - pm)
                     + psa[lane * 4 + 2] * (double)expf(pa2 - pm)
                     + psa[lane * 4 + 3] * (double)expf(pa3 - pm);
            for (int off = 16; off; off >>= 1)
                Z += __shfl_xor_sync(0xffffffffu, Z, off);
            if (lane == 0) {
                s_m[wrp] = pm;
                s_nbm[wrp] = pn;
                s_Z[wrp] = Z;
                s_sc[wrp] = g_scores2[par][wrp];
            }
            __syncthreads();
            if (wrp == 0 && lane < BB) {
                float m = s_m[lane];
                float lz = (float)log(s_Z[lane]);
                s_lz[lane] = lz;
                float t1 = (s_nbm[lane] - m) - lz;
                float t2 = ((g_mf[lane] - m) - lz) + NEGF;
                s_thr[lane] = fmaxf(t1, t2) - EXPANDF;
                s_blk[lane] = (g_blanklogit[lane] - m) - lz;
            }
            __syncthreads();
            float m = s_m[wrp], lz = s_lz[wrp], thr = s_thr[wrp], sc = s_sc[wrp];
            int c0 = lane, c1 = lane + 32;
            float x0 = s_logits[wrp][c0], x1 = s_logits[wrp][c1];
            float lp0 = (x0 - m) - lz;
            if (blk == 0 && c0 < 4) lp0 += NEGF;
            float lp1 = (x1 - m) - lz;
            float nb0 = lp0 > thr ? lp0 : NEGF;
            float nb1 = lp1 > thr ? lp1 : NEGF;
            int v0 = blk * 64 + c0, v1 = blk * 64 + c1;
            unsigned long long k0 = mkkey(sc + nb0, (unsigned)(wrp * (VV - 1) + v0));
            unsigned long long k1 = (v1 == VV - 1) ? 0ULL
                                  : mkkey(sc + nb1, (unsigned)(wrp * (VV - 1) + v1));
            for (int r = 0; r < BB; r++) {
                unsigned long long loc = k0 > k1 ? k0 : k1;
                for (int off = 16; off; off >>= 1) {
                    unsigned long long o = __shfl_xor_sync(0xffffffffu, loc, off);
                    if (o > loc) loc = o;
                }
                if (lane == r) s_stk[wrp * 16 + r] = loc;
                if (k0 == loc) k0 = 0ULL;
                if (k1 == loc) k1 = 0ULL;
            }
            __syncthreads();
            if (wrp == 0) {   // merge 256 -> 16
                unsigned long long kk[8];
#pragma unroll
                for (int j = 0; j < 8; j++) kk[j] = s_stk[lane + 32 * j];
                for (int r = 0; r < BB; r++) {
                    unsigned long long loc = kk[0];
#pragma unroll
                    for (int j = 1; j < 8; j++) if (kk[j] > loc) loc = kk[j];
                    for (int off = 16; off; off >>= 1) {
                        unsigned long long o = __shfl_xor_sync(0xffffffffu, loc, off);
                        if (o > loc) loc = o;
                    }
                    if (lane == r) g_part[blk * 16 + r] = loc;
#pragma unroll
                    for (int j = 0; j < 8; j++) if (kk[j] == loc) kk[j] = 0ULL;
                }
            }
        }
        gridbar();

        // ---- ph3: merge + select + LSTM GEMM (cp.async pipeline) + elem + apply ----
        {
            {
                unsigned long long kk[4];
#pragma unroll
                for (int j = 0; j < 4; j++) kk[j] = g_part[wrp * 128 + lane + 32 * j];
                for (int r = 0; r < BB; r++) {
                    unsigned long long loc = kk[0];
#pragma unroll
                    for (int j = 1; j < 4; j++) if (kk[j] > loc) loc = kk[j];
                    for (int off = 16; off; off >>= 1) {
                        unsigned long long o = __shfl_xor_sync(0xffffffffu, loc, off);
                        if (o > loc) loc = o;
                    }
                    if (lane == r) s_stk[wrp * 16 + r] = loc;
#pragma unroll
                    for (int j = 0; j < 4; j++) if (kk[j] == loc) kk[j] = 0ULL;
                }
            }
            __syncthreads();
            if (wrp == 0) {
                unsigned long long kk[8];
#pragma unroll
                for (int j = 0; j < 8; j++) kk[j] = s_stk[lane + 32 * j];
                for (int r = 0; r < BB; r++) {
                    unsigned long long loc = kk[0];
#pragma unroll
                    for (int j = 1; j < 8; j++) if (kk[j] > loc) loc = kk[j];
                    for (int off = 16; off; off >>= 1) {
                        unsigned long long o = __shfl_xor_sync(0xffffffffu, loc, off);
                        if (o > loc) loc = o;
                    }
                    if (lane == r) {
                        s_nbsc[r] = unordf((unsigned)(loc >> 32));
                        unsigned id = 0xFFFFFFFFu - (unsigned)(loc & 0xFFFFFFFFu);
                        s_nbhypo[r] = (int)(id / (VV - 1));
                        s_nbtok[r]  = (int)(id % (VV - 1));
                    }
#pragma unroll
                    for (int j = 0; j < 8; j++) if (kk[j] == loc) kk[j] = 0ULL;
                }
                __syncwarp();
                float val = (lane < BB) ? (s_sc[lane] + s_blk[lane]) : s_nbsc[lane - BB];
                unsigned long long key = mkkey(val, (unsigned)lane);
                for (int r = 0; r < BB; r++) {
                    unsigned long long loc = key;
                    for (int off = 16; off; off >>= 1) {
                        unsigned long long o = __shfl_xor_sync(0xffffffffu, loc, off);
                        if (o > loc) loc = o;
                    }
                    unsigned idx = 0xFFFFFFFFu - (unsigned)(loc & 0xFFFFFFFFu);
                    if (lane == r) {
                        s_newsc[r] = unordf((unsigned)(loc >> 32));
                        s_isblank[r] = (idx < BB) ? 1 : 0;
                        s_bsel[r] = (idx < BB) ? (int)idx : (BB - 1);
                        int n2 = (int)idx - BB;
                        n2 = n2 < 0 ? 0 : (n2 > BB - 1 ? BB - 1 : n2);
                        s_nsel[r] = n2;
                    }
                    if (lane == (int)idx) key = 0ULL;
                }
            }
            __syncthreads();
            if (blk == 0 && tid < BB) g_scores2[np][tid] = s_newsc[tid];

            // LSTM GEMM: 16 chunks x 64k, Wx then Wh same acc, cp.async staging
            const int quad = tid & 7, rgl = (tid >> 3) & 3, kc = tid >> 5;
            const unsigned long long* a0 = smp + (rgl * 4 + 0) * JP + kc * 64;
            const unsigned long long* a1 = a0 + JP;
            const unsigned long long* a2 = a1 + JP;
            const unsigned long long* a3 = a2 + JP;
            const unsigned long long* lwin = smp + WOFFU + wrp * 256;
            unsigned long long c00=0,c01=0,c10=0,c11=0,c20=0,c21=0,c30=0,c31=0;
            // prime Wx stages; overlap embed fill
            LFILL(Wx, 0); LFILL(Wx, 1); LFILL(Wx, 2);
#pragma unroll
            for (int j = 0; j < 8; j++) {
                int unit = j * NTHR + tid;
                int row = unit >> 8, k = (unit & 255) * 4;
                float4 v = *(const float4*)&embed[(size_t)s_nbtok[row] * HH + k];
                ulonglong2* dst = (ulonglong2*)(smp + row * JP + k);
                dst[0] = make_ulonglong2(pk2(v.x), pk2(v.y));
                dst[1] = make_ulonglong2(pk2(v.z), pk2(v.w));
            }
            __syncthreads();
#pragma unroll 1
            for (int s = 0; s < 16; s++) {
                if (s <= 13) cpwait<2>();
                else if (s == 14) cpwait<1>();
                else cpwait<0>();
                __syncwarp();
                const unsigned long long* wsl = lwin + (s & 3) * 64 + quad * 2;
                ulonglong2 W[4];
                W[0] = *(const ulonglong2*)(wsl +  0);
                W[1] = *(const ulonglong2*)(wsl + 16);
                W[2] = *(const ulonglong2*)(wsl + 32);
                W[3] = *(const ulonglong2*)(wsl + 48);
                CONSUME(W, s * 4);
                if (s < 13) LFILL(Wx, s + 3);
            }
            __syncthreads();
            // prime Wh stages; overlap h fill
            LFILL(Wh, 0); LFILL(Wh, 1); LFILL(Wh, 2);
            {
                const float* hs = g_h[par];
#pragma unroll
                for (int j = 0; j < 8; j++) {
                    int unit = j * NTHR + tid;
                    int row = unit >> 8, k = (unit & 255) * 4;
                    float4 v = *(const float4*)&hs[s_nbhypo[row] * HH + k];
                    ulonglong2* dst = (ulonglong2*)(smp + row * JP + k);
                    dst[0] = make_ulonglong2(pk2(v.x), pk2(v.y));
                    dst[1] = make_ulonglong2(pk2(v.z), pk2(v.w));
                }
            }
            __syncthreads();
#pragma unroll 1
            for (int s = 0; s < 16; s++) {
                if (s <= 13) cpwait<2>();
                else if (s == 14) cpwait<1>();
                else cpwait<0>();
                __syncwarp();
                const unsigned long long* wsl = lwin + (s & 3) * 64 + quad * 2;
                ulonglong2 W[4];
                W[0] = *(const ulonglong2*)(wsl +  0);
                W[1] = *(const ulonglong2*)(wsl + 16);
                W[2] = *(const ulonglong2*)(wsl + 32);
                W[3] = *(const ulonglong2*)(wsl + 48);
                CONSUME(W, s * 4);
                if (s < 13) LFILL(Wh, s + 3);
            }
            __syncthreads();
            float* sred = (float*)smp;
            STORE_PARTIALS(sred, (kc * 32 + rgl * 8 + quad) * PS);
            __syncthreads();
            if (tid < 128) {
                int row = tid >> 3, quado = tid & 7;
                int rglo = row >> 2, r = row & 3;
                float s0 = 0.f, s1 = 0.f, s2 = 0.f, s3 = 0.f;
#pragma unroll
                for (int k16 = 0; k16 < 16; k16++) {
                    float4 f = *(const float4*)
                        &sred[(k16 * 32 + rglo * 8 + quado) * PS + r * 4];
                    s0 += f.x; s1 += f.y; s2 += f.z; s3 += f.w;
                }
                int gateo = quado >> 1;
                int u0 = (quado & 1) * 4;
                s_gates[row][gateo * 8 + u0 + 0] = s0 + blstm[gateo * 1024 + blk * 8 + u0 + 0];
                s_gates[row][gateo * 8 + u0 + 1] = s1 + blstm[gateo * 1024 + blk * 8 + u0 + 1];
                s_gates[row][gateo * 8 + u0 + 2] = s2 + blstm[gateo * 1024 + blk * 8 + u0 + 2];
                s_gates[row][gateo * 8 + u0 + 3] = s3 + blstm[gateo * 1024 + blk * 8 + u0 + 3];
            }
            __syncthreads();
            {
                int cell = tid >> 2, gsel = tid & 3;
                int j = cell >> 3, uo = cell & 7;
                float gval = s_gates[j][gsel * 8 + uo];
                s_act[cell][gsel] = (gsel == 2) ? tanh_acc(gval) : sigf(gval);
            }
            __syncthreads();
            if (tid < 128) {
                int j2 = tid >> 3, uo2 = tid & 7, u2 = blk * 8 + uo2;
                float cp = g_c[par][s_nbhypo[j2] * HH + u2];
                float cc = s_act[tid][1] * cp + s_act[tid][0] * s_act[tid][2];
                nc_s[j2][uo2] = cc;
                nh_s[j2][uo2] = s_act[tid][3] * tanh_acc(cc);
            }
            __syncthreads();
            if (tid < 128) {
                int i2 = tid >> 3, uo2 = tid & 7, u2 = blk * 8 + uo2;
                float hn, cn;
                if (s_isblank[i2]) {
                    hn = g_h[par][s_bsel[i2] * HH + u2];
                    cn = g_c[par][s_bsel[i2] * HH + u2];
                } else {
                    int ns = s_nsel[i2];
                    hn = nh_s[ns][uo2]; cn = nc_s[ns][uo2];
                }
                g_h[np][i2 * HH + u2] = hn;
                g_c[np][i2 * HH + u2] = cn;
            }
            if (tid < 64) {
                int i2 = tid >> 2, sl = blk * 4 + (tid & 3);
                int tok;
                if (s_isblank[i2]) {
                    tok = g_tokens[par][s_bsel[i2] * TT + sl];
                } else {
                    int ns = s_nsel[i2];
                    tok = (sl == t) ? s_nbtok[ns] : g_tokens[par][s_nbhypo[ns] * TT + sl];
                }
                g_tokens[np][i2 * TT + sl] = tok;
            }
        }
        gridbar();
    }

    // ================= epilogue =================
    if (blk == 0) {
        for (int e = tid; e < BB; e += NTHR) out[e] = g_scores2[0][e];
        for (int e = tid; e < BB * TT; e += NTHR) out[BB + e] = (float)g_tokens[0][e];
    }
}

// ---------------- host ----------------
extern "C" void kernel_launch(void* const* d_in, const int* in_sizes, int n_in,
                              void* d_out, int out_size) {
    const float* input   = (const float*)d_in[0];
    const float* enc_W   = (const float*)d_in[1];
    const float* enc_b   = (const float*)d_in[2];
    const float* embed   = (const float*)d_in[3];
    const float* Wx      = (const float*)d_in[4];
    const float* Wh      = (const float*)d_in[5];
    const float* b_lstm  = (const float*)d_in[6];
    const float* joint_W = (const float*)d_in[7];
    const float* joint_b = (const float*)d_in[8];
    (void)in_sizes; (void)n_in; (void)out_size;

    cudaFuncSetAttribute(rnnt_persist, cudaFuncAttributeMaxDynamicSharedMemorySize, DYN_SMEM);
    rnnt_persist<<<NBLK, NTHR, DYN_SMEM>>>(input, enc_W, enc_b, embed, Wx, Wh,
                                           b_lstm, joint_W, joint_b, (float*)d_out);
}